// round 7
// baseline (speedup 1.0000x reference)
#include <cuda_runtime.h>
#include <cstddef>

// ---------------- problem constants ----------------
#define H       512
#define IDIM    128
#define KIN     640          // H + I
#define SEQ     256
#define OUTLEN  64
#define CDIM    64
#define BATCH   32
#define NSTEPS  (SEQ + OUTLEN)

// ---------------- partition: 64 CTAs, 2 chains (batch groups) per CTA ------
#define GROUPS  4                  // batch groups (chains)
#define PCOLS   32                 // column CTAs per chain
#define BG      (BATCH / GROUPS)   // 8 batch rows per chain
#define COLS    (H / PCOLS)        // 16 hidden cols per CTA
#define OUTC    (CDIM / PCOLS)     // 2 output cols per CTA
#define NCTAS   64                 // 32 col-CTAs x 2 chain-pairs
#define TPB     256
#define RING_D  17                 // exact delay-line depth (mod-17 wrap)

// padded SMEM strides (floats)
#define WS_IN   644          // KIN + 4
#define WS_H    516          // H + 4

#define SCR_FLOATS 4352      // max(128*33, 256*17)

// ---------------- SMEM layout (floats) ----------------
#define OFF_WIN    0                               // 16*644 = 10304
#define OFF_WPASS  (OFF_WIN   + COLS * WS_IN)      // 10304
#define OFF_WTAU   (OFF_WPASS + COLS * WS_H)       // 18560
#define OFF_WMEM   (OFF_WTAU  + COLS * WS_H)       // 26816
#define OFF_WOUT   (OFF_WMEM  + COLS * WS_H)       // 35072 (+1032)
#define OFF_BIAS   (OFF_WOUT  + OUTC * WS_H)       // 36104 (+80)
#define OFF_SCR    (OFF_BIAS  + 80)                // 36184 (+4352)
// per-chain block
#define CH_HS      0                               // BG*KIN = 5120
#define CH_TH      5120
#define CH_THPRE   5248
#define CH_GT      5376
#define CH_GM      5504
#define CH_RING    5632                            // 17*128 = 2176
#define CH_SLEN    7808                            // 8 ints
#define CH_SIZE    7816
#define OFF_CH0    (OFF_SCR + SCR_FLOATS)          // 40536
#define OFF_CH1    (OFF_CH0 + CH_SIZE)             // 48352
#define SMEM_FLOATS (OFF_CH1 + CH_SIZE)            // 56168
#define SMEM_BYTES  (SMEM_FLOATS * 4)              // 224672 B < 227 KB

typedef unsigned long long ull;

// ---------------- global staging + flags ----------------
__device__ __align__(16) float g_h0  [GROUPS][BG * H];
__device__ __align__(16) float g_hpre[GROUPS][BG * H];
__device__ __align__(16) float g_hmix[GROUPS][BG * H];

// one monotonic flag per (chain, col-CTA), padded to a 128B line
__device__ unsigned g_flg[GROUPS * PCOLS * 32];

struct __align__(128) AllBar { unsigned count; unsigned sense; unsigned pad[30]; };
__device__ AllBar g_allbar;

__device__ __forceinline__ float sigf(float z) { return 1.f / (1.f + __expf(-z)); }

__device__ __forceinline__ void st_rel(unsigned* a, unsigned v) {
    asm volatile("st.release.gpu.global.u32 [%0], %1;" :: "l"(a), "r"(v) : "memory");
}
__device__ __forceinline__ unsigned ld_acq(const unsigned* a) {
    unsigned v;
    asm volatile("ld.acquire.gpu.global.u32 %0, [%1];" : "=r"(v) : "l"(a) : "memory");
    return v;
}

#define PUBLISHG(gg, val)                                                       \
    do {                                                                        \
        __syncthreads();                                                        \
        if (tid == 0) st_rel(&g_flg[((gg) * PCOLS + p) * 32], (unsigned)(val)); \
    } while (0)

#define WAITG(gg, val)                                                          \
    do {                                                                        \
        if (tid < PCOLS) {                                                      \
            const unsigned* fp = &g_flg[((gg) * PCOLS + tid) * 32];             \
            while (ld_acq(fp) < (unsigned)(val)) { }                            \
        }                                                                       \
        __syncthreads();                                                        \
    } while (0)

// packed dual-FMA: acc(2xf32) += h(2xf32) * w(2xf32)
__device__ __forceinline__ void fma2pk(ull& acc, double h, double w)
{
    asm("fma.rn.f32x2 %0, %1, %2, %0;"
        : "+l"(acc)
        : "l"(__double_as_longlong(h)), "l"(__double_as_longlong(w)));
}
__device__ __forceinline__ float pk_sum(ull a)
{
    float lo = __uint_as_float((unsigned)(a & 0xffffffffu));
    float hi = __uint_as_float((unsigned)(a >> 32));
    return lo + hi;
}
__device__ __forceinline__ void fma16x2(const double2 hd[4], const double2 wd[4],
                                        ull acc[4][4])
{
#pragma unroll
    for (int r = 0; r < 4; ++r)
#pragma unroll
        for (int c = 0; c < 4; ++c) {
            fma2pk(acc[r][c], hd[r].x, wd[c].x);
            fma2pk(acc[r][c], hd[r].y, wd[c].y);
        }
}

extern "C" __global__ void __launch_bounds__(TPB, 1)
delay_rnn_kernel(const float* __restrict__ x,       // [B, S, I]
                 const int*   __restrict__ lengths, // [B]
                 const float* __restrict__ W_in,    // [KIN, H]
                 const float* __restrict__ b_in,
                 const float* __restrict__ W_pass,  // [H, H]
                 const float* __restrict__ b_pass,
                 const float* __restrict__ W_tau,
                 const float* __restrict__ b_tau,
                 const float* __restrict__ W_mem,
                 const float* __restrict__ b_mem,
                 const float* __restrict__ W_out,   // [H, C]
                 const float* __restrict__ b_out,
                 float*       __restrict__ out)     // [B, OUTLEN, C]
{
    extern __shared__ float sm[];
    const int tid     = threadIdx.x;
    const int cta     = blockIdx.x;
    const int p       = cta & 31;        // column partition
    const int gp      = cta >> 5;        // chain-pair id (0/1)
    const int g0      = 2 * gp, g1 = 2 * gp + 1;
    const int b00     = g0 * BG, b01 = g1 * BG;
    const int colbase = p * COLS;
    const int oc0     = p * OUTC;

    float* sWin   = sm + OFF_WIN;
    float* sWpass = sm + OFF_WPASS;
    float* sWtau  = sm + OFF_WTAU;
    float* sWmem  = sm + OFF_WMEM;
    float* sWout  = sm + OFF_WOUT;
    float* sbin   = sm + OFF_BIAS;
    float* sbpass = sbin + 16;
    float* sbtau  = sbpass + 16;
    float* sbmem  = sbtau + 16;
    float* sbout  = sbmem + 16;           // 4 (2 used)
    float* scr    = sm + OFF_SCR;
    float* ch0    = sm + OFF_CH0;
    float* ch1    = sm + OFF_CH1;

    // ---- prologue: shared weights -> SMEM (transposed, padded) ----
    for (int idx = tid; idx < KIN * COLS; idx += TPB) {
        int k = idx >> 4, cl = idx & 15;
        sWin[cl * WS_IN + k] = W_in[k * H + colbase + cl];
    }
    for (int idx = tid; idx < H * COLS; idx += TPB) {
        int k = idx >> 4, cl = idx & 15;
        sWpass[cl * WS_H + k] = W_pass[k * H + colbase + cl];
        sWtau [cl * WS_H + k] = W_tau [k * H + colbase + cl];
        sWmem [cl * WS_H + k] = W_mem [k * H + colbase + cl];
    }
    for (int idx = tid; idx < H * OUTC; idx += TPB) {
        int k = idx >> 1, c = idx & 1;
        sWout[c * WS_H + k] = W_out[k * CDIM + oc0 + c];
    }
    if (tid < 16) {
        sbin[tid]   = b_in  [colbase + tid];
        sbpass[tid] = b_pass[colbase + tid];
        sbtau[tid]  = b_tau [colbase + tid];
        sbmem[tid]  = b_mem [colbase + tid];
    }
    if (tid < OUTC) sbout[tid] = b_out[oc0 + tid];
    if (tid < BG) {
        ((int*)(ch0 + CH_SLEN))[tid] = lengths[b00 + tid];
        ((int*)(ch1 + CH_SLEN))[tid] = lengths[b01 + tid];
    }
    for (int idx = tid; idx < RING_D * 128; idx += TPB) {
        ch0[CH_RING + idx] = 0.f;
        ch1[CH_RING + idx] = 0.f;
    }
    if (tid < 128) {  // initial h0 = 0 for both chains
        int row = tid >> 4, cl = tid & 15;
        g_h0[g0][row * H + colbase + cl] = 0.f;
        g_h0[g1][row * H + colbase + cl] = 0.f;
    }

    unsigned bsense = 0;
    if (tid == 0) bsense = *(volatile unsigned*)&g_allbar.sense;

    PUBLISHG(g0, 1);
    PUBLISHG(g1, 1);

    // tile coordinates (fixed per thread)
    const int sA  = tid & 31;             // split id, phases A/B (32-way)
    const int tlA = tid >> 5;
    const int rA  = (tlA & 1) * 4;
    const int cA  = (tlA >> 1) * 4;

    const int sC  = tid & 15;             // split id, phase C (16-way)
    const int tlC = tid >> 4;
    const int rC  = (tlC & 1) * 4;
    const int cC  = (tlC >> 1) * 4;       // 0..28 over 32 logical cols

    const int oR   = tid >> 1;            // paired-reduction output id
    const int hR   = tid & 1;
    const int rowR = oR >> 4, clR = oR & 15;

    // ---------------- per-chain phase lambdas ----------------
    auto phaseA = [&](int cg, int cb0, float* ch, int st, bool enc) {
        float* chs    = ch + CH_HS;
        float* cthpre = ch + CH_THPRE;
        if (enc) {   // x_t prefetch BEFORE the flag wait
            int row = tid >> 5, iq = tid & 31;
            float4 v = __ldg((const float4*)(x + ((size_t)(cb0 + row) * SEQ + st) * IDIM) + iq);
            *((float4*)(chs + row * KIN + H) + iq) = v;
        }
        WAITG(cg, 3 * st + 1);
        for (int i = tid; i < (BG * H) / 4; i += TPB) {
            int row = i >> 7, kq = i & 127;
            *((float4*)(chs + row * KIN) + kq) = __ldcg((const float4*)g_h0[cg] + i);
        }
        __syncthreads();

        ull acc[4][4] = {};
        const int nj = enc ? 5 : 4;
        for (int j = 0; j < nj; ++j) {
            const int k = sA * 4 + j * 128;
            double2 hd[4], wd[4];
#pragma unroll
            for (int r = 0; r < 4; ++r)
                hd[r] = *(const double2*)(chs + (rA + r) * KIN + k);
#pragma unroll
            for (int c = 0; c < 4; ++c)
                wd[c] = *(const double2*)(sWin + (cA + c) * WS_IN + k);
            fma16x2(hd, wd, acc);
        }
#pragma unroll
        for (int r = 0; r < 4; ++r)
#pragma unroll
            for (int c = 0; c < 4; ++c)
                scr[((rA + r) * 16 + cA + c) * 33 + sA] = pk_sum(acc[r][c]);
        __syncthreads();

        {   // paired reduction
            float v = 0.f;
#pragma unroll
            for (int s2 = 0; s2 < 16; ++s2) v += scr[oR * 33 + hR * 16 + s2];
            v += __shfl_xor_sync(0xffffffffu, v, 1);
            if (hR == 0) {
                float hv = v + sbin[clR];
                cthpre[oR] = hv;
                g_hpre[cg][rowR * H + colbase + clR] = hv;
            }
        }
        PUBLISHG(cg, 3 * st + 2);
    };

    auto decodeOut = [&](int cb0, float* ch, int st) {
        float* chs = ch + CH_HS;          // still holds h0 staged by phaseA
        __syncthreads();
        const int oo = tid >> 4, kp = tid & 15;
        const int row = oo >> 1, c = oo & 1;
        const float* hr = chs + row * KIN + kp * 32;
        const float* wr = sWout + c * WS_H + kp * 32;
        float a = 0.f;
#pragma unroll
        for (int k = 0; k < 32; k += 4) {
            float4 h4 = *(const float4*)(hr + k);
            float4 w4 = *(const float4*)(wr + k);
            a = fmaf(h4.x, w4.x, a); a = fmaf(h4.y, w4.y, a);
            a = fmaf(h4.z, w4.z, a); a = fmaf(h4.w, w4.w, a);
        }
        scr[tid] = a;
        __syncthreads();
        if (tid < 16) {
            float s = 0.f;
#pragma unroll
            for (int j = 0; j < 16; ++j) s += scr[tid * 16 + j];
            const int row2 = tid >> 1, c2 = tid & 1;
            const int td = st - SEQ;
            out[((size_t)(cb0 + row2) * OUTLEN + td) * CDIM + oc0 + c2] = s + sbout[c2];
        }
    };

    auto phaseB = [&](int cg, float* ch, int st, bool enc) {
        float* chs    = ch + CH_HS;
        float* cth    = ch + CH_TH;
        float* cthpre = ch + CH_THPRE;
        const int* cslen = (const int*)(ch + CH_SLEN);
        WAITG(cg, 3 * st + 2);
        for (int i = tid; i < (BG * H) / 4; i += TPB) {
            int row = i >> 7, kq = i & 127;
            *((float4*)(chs + row * KIN) + kq) = __ldcg((const float4*)g_hpre[cg] + i);
        }
        __syncthreads();

        ull acc[4][4] = {};
#pragma unroll
        for (int j = 0; j < 4; ++j) {
            const int k = sA * 4 + j * 128;
            double2 hd[4], wd[4];
#pragma unroll
            for (int r = 0; r < 4; ++r)
                hd[r] = *(const double2*)(chs + (rA + r) * KIN + k);
#pragma unroll
            for (int c = 0; c < 4; ++c)
                wd[c] = *(const double2*)(sWpass + (cA + c) * WS_H + k);
            fma16x2(hd, wd, acc);
        }
#pragma unroll
        for (int r = 0; r < 4; ++r)
#pragma unroll
            for (int c = 0; c < 4; ++c)
                scr[((rA + r) * 16 + cA + c) * 33 + sA] = pk_sum(acc[r][c]);
        __syncthreads();

        {   // paired reduction + mask mixing
            float v = 0.f;
#pragma unroll
            for (int s2 = 0; s2 < 16; ++s2) v += scr[oR * 33 + hR * 16 + s2];
            v += __shfl_xor_sync(0xffffffffu, v, 1);
            if (hR == 0) {
                float pv = v + sbpass[clR];
                float hv;
                if (enc) {
                    float m = (st < cslen[rowR]) ? 1.f : 0.f;
                    hv = m * pv + (1.f - m) * cthpre[oR];
                } else {
                    hv = pv;
                }
                cth[oR] = hv;
                g_hmix[cg][rowR * H + colbase + clR] = hv;
            }
        }
        PUBLISHG(cg, 3 * st + 3);
    };

    auto phaseC = [&](int cg, float* ch, int st, int rb) {
        float* chs   = ch + CH_HS;
        float* cth   = ch + CH_TH;
        float* cgt   = ch + CH_GT;
        float* cgm   = ch + CH_GM;
        float* cring = ch + CH_RING;
        WAITG(cg, 3 * st + 3);
        for (int i = tid; i < (BG * H) / 4; i += TPB) {
            int row = i >> 7, kq = i & 127;
            *((float4*)(chs + row * KIN) + kq) = __ldcg((const float4*)g_hmix[cg] + i);
        }
        __syncthreads();

        ull acc[4][4] = {};
#pragma unroll
        for (int j = 0; j < 8; ++j) {
            const int k = sC * 4 + j * 64;
            double2 hd[4], wd[4];
#pragma unroll
            for (int r = 0; r < 4; ++r)
                hd[r] = *(const double2*)(chs + (rC + r) * KIN + k);
#pragma unroll
            for (int c = 0; c < 4; ++c) {
                const int lc = cC + c;
                const float* wb = (lc < 16) ? (sWtau + lc * WS_H)
                                            : (sWmem + (lc - 16) * WS_H);
                wd[c] = *(const double2*)(wb + k);
            }
            fma16x2(hd, wd, acc);
        }
#pragma unroll
        for (int r = 0; r < 4; ++r)
#pragma unroll
            for (int c = 0; c < 4; ++c)
                scr[((rC + r) * 32 + cC + c) * 17 + sC] = pk_sum(acc[r][c]);
        __syncthreads();

        {   // reduction + gate nonlinearity
            const int row = tid >> 5, lc = tid & 31;
            float v = 0.f;
#pragma unroll 8
            for (int s2 = 0; s2 < 16; ++s2) v += scr[tid * 17 + s2];
            if (lc < 16) {
                v += sbtau[lc];
                cgt[row * 16 + lc] = fminf(fmaxf(16.f * sigf(v), 1.f), 16.f);
            } else {
                v += sbmem[lc - 16];
                cgm[row * 16 + (lc - 16)] = sigf(v);
            }
        }
        __syncthreads();

        if (tid < 128) {
            const float tau = cgt[tid];
            const float ml  = cgm[tid];
            const float hv  = cth[tid];
            cring[rb * 128 + tid] = 0.f;          // retire consumed slot
#pragma unroll
            for (int jp = 1; jp <= 16; ++jp) {
                int s = rb + jp; if (s >= RING_D) s -= RING_D;
                const float w = ml / (1.f + fabsf(tau - (float)jp));
                cring[s * 128 + tid] += w * hv;
            }
            int s1 = rb + 1; if (s1 >= RING_D) s1 -= RING_D;
            const float h0n = cring[s1 * 128 + tid];
            const int row2 = tid >> 4, cl2 = tid & 15;
            g_h0[cg][row2 * H + colbase + cl2] = h0n;
        }
        PUBLISHG(cg, 3 * st + 4);
    };

    // ---------------- main loop: interleave the two chains ----------------
    int rb = 0;
    for (int st = 0; st < NSTEPS; ++st) {
        const bool enc = (st < SEQ);

        phaseA(g0, b00, ch0, st, enc);
        if (!enc) decodeOut(b00, ch0, st);
        phaseA(g1, b01, ch1, st, enc);
        if (!enc) decodeOut(b01, ch1, st);

        phaseB(g0, ch0, st, enc);
        phaseB(g1, ch1, st, enc);

        phaseC(g0, ch0, st, rb);
        phaseC(g1, ch1, st, rb);

        rb = (rb + 1 == RING_D) ? 0 : rb + 1;
    }

    // drain all CTAs, then reset flags for the next graph replay
    __threadfence();
    __syncthreads();
    if (tid == 0) {
        unsigned ns = bsense ^ 1u;
        if (atomicAdd(&g_allbar.count, 1u) == (unsigned)(NCTAS - 1)) {
            g_allbar.count = 0u;
            __threadfence();
            atomicExch(&g_allbar.sense, ns);
        } else {
            while (*(volatile unsigned*)&g_allbar.sense != ns) { }
        }
        g_flg[(g0 * PCOLS + p) * 32] = 0u;
        g_flg[(g1 * PCOLS + p) * 32] = 0u;
    }
}

extern "C" void kernel_launch(void* const* d_in, const int* in_sizes, int n_in,
                              void* d_out, int out_size)
{
    int wi = 2;
    if (n_in > 2 && in_sizes[2] == 1) wi = 3;   // skip scalar out_lengths if present

    const float* x       = (const float*)d_in[0];
    const int*   lengths = (const int*)  d_in[1];
    const float* W_in    = (const float*)d_in[wi + 0];
    const float* b_in    = (const float*)d_in[wi + 1];
    const float* W_pass  = (const float*)d_in[wi + 2];
    const float* b_pass  = (const float*)d_in[wi + 3];
    const float* W_tau   = (const float*)d_in[wi + 4];
    const float* b_tau   = (const float*)d_in[wi + 5];
    const float* W_mem   = (const float*)d_in[wi + 6];
    const float* b_mem   = (const float*)d_in[wi + 7];
    const float* W_out   = (const float*)d_in[wi + 8];
    const float* b_out   = (const float*)d_in[wi + 9];

    cudaFuncSetAttribute(delay_rnn_kernel,
                         cudaFuncAttributeMaxDynamicSharedMemorySize, SMEM_BYTES);

    delay_rnn_kernel<<<NCTAS, TPB, SMEM_BYTES>>>(
        x, lengths, W_in, b_in, W_pass, b_pass, W_tau, b_tau,
        W_mem, b_mem, W_out, b_out, (float*)d_out);
}

// round 10
// speedup vs baseline: 2.2433x; 2.2433x over previous
#include <cuda_runtime.h>
#include <cstddef>

// ---------------- problem constants ----------------
#define H       512
#define IDIM    128
#define KIN     640          // H + I
#define SEQ     256
#define OUTLEN  64
#define CDIM    64
#define BATCH   32
#define NSTEPS  (SEQ + OUTLEN)

// ---------------- partition: 128 CTAs, one chain per CTA ----------------
#define GROUPS  4                  // batch groups (chains)
#define PCOLS   32                 // column CTAs per chain
#define BG      (BATCH / GROUPS)   // 8 batch rows per chain
#define COLS    (H / PCOLS)        // 16 hidden cols per CTA
#define OUTC    (CDIM / PCOLS)     // 2 output cols per CTA
#define NCTAS   (GROUPS * PCOLS)   // 128
#define TPB     256
#define RINGD   32                 // ring depth (power of two >= 17)

// padded SMEM strides (floats)
#define WS_IN   644          // KIN + 4
#define WS_H    516          // H + 4

#define SCR_FLOATS 4352      // 256 outputs x 17

// ---------------- SMEM layout (floats) ----------------
#define OFF_WIN    0                                // 10304
#define OFF_WFP    (OFF_WIN  + COLS * WS_IN)        // fused W_in@W_pass, 10304
#define OFF_WTAU   (OFF_WFP  + COLS * WS_IN)        // 8256
#define OFF_WMEM   (OFF_WTAU + COLS * WS_H)         // 8256
#define OFF_WOUT   (OFF_WMEM + COLS * WS_H)         // 1032
#define OFF_BIAS   (OFF_WOUT + OUTC * WS_H)         // 80
#define OFF_HS     (OFF_BIAS + 80)                  // 8*KIN = 5120
#define OFF_TH     (OFF_HS   + BG * KIN)            // 128
#define OFF_TMP    (OFF_TH   + 128)                 // 256
#define OFF_GT     (OFF_TMP  + 256)                 // 128
#define OFF_GM     (OFF_GT   + 128)                 // 128
#define OFF_SCR    (OFF_GM   + 128)                 // 4352
#define OFF_RING   (OFF_SCR  + SCR_FLOATS)          // 32*128 = 4096
#define SMEM_FLOATS (OFF_RING + RINGD * 128)
#define SMEM_BYTES  (SMEM_FLOATS * 4)               // ~210 KB < 227 KB

typedef unsigned long long ull;

// ---------------- global staging + flags ----------------
__device__ __align__(16) float g_h0  [GROUPS][BG * H];
__device__ __align__(16) float g_hmix[GROUPS][BG * H];
__device__ __align__(16) float g_wfp [H * KIN];      // fused W_in@W_pass, [col][k]

// one monotonic flag per (chain, col-CTA), padded to a 128B line
__device__ unsigned g_flg[GROUPS * PCOLS * 32];

struct __align__(128) AllBar { unsigned count; unsigned sense; unsigned pad[30]; };
__device__ AllBar g_allbar;

__device__ __forceinline__ float sigf(float z) { return 1.f / (1.f + __expf(-z)); }

__device__ __forceinline__ void st_rel(unsigned* a, unsigned v) {
    asm volatile("st.release.gpu.global.u32 [%0], %1;" :: "l"(a), "r"(v) : "memory");
}
__device__ __forceinline__ unsigned ld_acq(const unsigned* a) {
    unsigned v;
    asm volatile("ld.acquire.gpu.global.u32 %0, [%1];" : "=r"(v) : "l"(a) : "memory");
    return v;
}

#define PUBLISH(val)                                                           \
    do {                                                                       \
        __syncthreads();                                                       \
        if (tid == 0) st_rel(&g_flg[(g * PCOLS + p) * 32], (unsigned)(val));   \
    } while (0)

#define WAIT_FLAGS(val)                                                        \
    do {                                                                       \
        if (tid < PCOLS) {                                                     \
            const unsigned* fp = &g_flg[(g * PCOLS + tid) * 32];               \
            while (ld_acq(fp) < (unsigned)(val)) { }                           \
        }                                                                      \
        __syncthreads();                                                       \
    } while (0)

// packed dual-FMA: acc(2xf32) += h(2xf32) * w(2xf32)
__device__ __forceinline__ void fma2pk(ull& acc, double h, double w)
{
    asm("fma.rn.f32x2 %0, %1, %2, %0;"
        : "+l"(acc)
        : "l"(__double_as_longlong(h)), "l"(__double_as_longlong(w)));
}
__device__ __forceinline__ float pk_sum(ull a)
{
    float lo = __uint_as_float((unsigned)(a & 0xffffffffu));
    float hi = __uint_as_float((unsigned)(a >> 32));
    return lo + hi;
}
__device__ __forceinline__ void fma16x2(const double2 hd[4], const double2 wd[4],
                                        ull acc[4][4])
{
#pragma unroll
    for (int r = 0; r < 4; ++r)
#pragma unroll
        for (int c = 0; c < 4; ++c) {
            fma2pk(acc[r][c], hd[r].x, wd[c].x);
            fma2pk(acc[r][c], hd[r].y, wd[c].y);
        }
}

extern "C" __global__ void __launch_bounds__(TPB, 1)
delay_rnn_kernel(const float* __restrict__ x,       // [B, S, I]
                 const int*   __restrict__ lengths, // [B]
                 const float* __restrict__ W_in,    // [KIN, H]
                 const float* __restrict__ b_in,
                 const float* __restrict__ W_pass,  // [H, H]
                 const float* __restrict__ b_pass,
                 const float* __restrict__ W_tau,
                 const float* __restrict__ b_tau,
                 const float* __restrict__ W_mem,
                 const float* __restrict__ b_mem,
                 const float* __restrict__ W_out,   // [H, C]
                 const float* __restrict__ b_out,
                 float*       __restrict__ out)     // [B, OUTLEN, C]
{
    extern __shared__ float sm[];
    const int tid     = threadIdx.x;
    const int cta     = blockIdx.x;
    const int g       = cta >> 5;        // chain id
    const int p       = cta & 31;        // column partition
    const int b0      = g * BG;
    const int colbase = p * COLS;
    const int oc0     = p * OUTC;
    const int wfc0    = cta * 4;         // 4 fused cols computed by this CTA

    float* sWin  = sm + OFF_WIN;
    float* sWfp  = sm + OFF_WFP;
    float* sWtau = sm + OFF_WTAU;
    float* sWmem = sm + OFF_WMEM;
    float* sWout = sm + OFF_WOUT;
    float* sbin  = sm + OFF_BIAS;         // 16
    float* sbp   = sbin + 16;             // 16 (fused p bias)
    float* sbtau = sbp + 16;              // 16
    float* sbmem = sbtau + 16;            // 16
    float* sbout = sbmem + 16;            // 4 (2 used)
    int*   slen  = (int*)(sbout + 4);     // 8
    float* chs   = sm + OFF_HS;
    float* t_h   = sm + OFF_TH;
    float* tmp   = sm + OFF_TMP;
    float* g_t   = sm + OFF_GT;
    float* g_m   = sm + OFF_GM;
    float* scr   = sm + OFF_SCR;
    float* ring  = sm + OFF_RING;

    unsigned bsense = 0;
    if (tid == 0) bsense = *(volatile unsigned*)&g_allbar.sense;

    auto ALLBAR = [&]() {
        __threadfence();
        __syncthreads();
        if (tid == 0) {
            unsigned ns = bsense ^ 1u;
            bsense = ns;
            if (atomicAdd(&g_allbar.count, 1u) == (unsigned)(NCTAS - 1)) {
                g_allbar.count = 0u;
                __threadfence();
                atomicExch(&g_allbar.sense, ns);
            } else {
                while (*(volatile unsigned*)&g_allbar.sense != ns) { }
            }
        }
        __syncthreads();
    };

    // ---- prologue: base weights -> SMEM (transposed, padded) ----
    for (int idx = tid; idx < KIN * COLS; idx += TPB) {
        int k = idx >> 4, cl = idx & 15;
        sWin[cl * WS_IN + k] = W_in[k * H + colbase + cl];
    }
    for (int idx = tid; idx < H * COLS; idx += TPB) {
        int k = idx >> 4, cl = idx & 15;
        sWtau[cl * WS_H + k] = W_tau[k * H + colbase + cl];
        sWmem[cl * WS_H + k] = W_mem[k * H + colbase + cl];
    }
    for (int idx = tid; idx < H * OUTC; idx += TPB) {
        int k = idx >> 1, c = idx & 1;
        sWout[c * WS_H + k] = W_out[k * CDIM + oc0 + c];
    }
    if (tid < 16) {
        sbin[tid]  = b_in [colbase + tid];
        sbtau[tid] = b_tau[colbase + tid];
        sbmem[tid] = b_mem[colbase + tid];
    }
    if (tid < OUTC) sbout[tid] = b_out[oc0 + tid];
    if (tid < BG)   slen[tid]  = lengths[b0 + tid];
    for (int idx = tid; idx < RINGD * 128; idx += TPB) ring[idx] = 0.f;
    if (tid < 128) {  // initial h0 = 0
        int row = tid >> 4, cl = tid & 15;
        g_h0[g][row * H + colbase + cl] = 0.f;
    }
    PUBLISH(1);   // h0 slice ready (early, so no one stalls at step 0)

    // ---- fused p-bias: bp = b_in @ W_pass + b_pass (this CTA's 16 cols) ----
    {
        const int c = tid & 15, sj = tid >> 4;    // 16 splits of 32 j's
        float a = 0.f;
        for (int j = sj * 32; j < sj * 32 + 32; ++j)
            a = fmaf(b_in[j], W_pass[j * H + colbase + c], a);
        tmp[c * 16 + sj] = a;
        __syncthreads();
        if (tid < 16) {
            float s = b_pass[colbase + tid];
#pragma unroll
            for (int i = 0; i < 16; ++i) s += tmp[tid * 16 + i];
            sbp[tid] = s;
        }
        __syncthreads();
    }

    // ---- fused weight: Wf = W_in @ W_pass, this CTA computes cols [wfc0, wfc0+4) ----
    {
        // stage the 4 W_pass columns (transposed) into scr
        for (int idx = tid; idx < 4 * H; idx += TPB) {
            int j = idx >> 2, c = idx & 3;
            scr[c * H + j] = W_pass[j * H + wfc0 + c];
        }
        __syncthreads();
        for (int k = tid; k < KIN; k += TPB) {
            float a0 = 0.f, a1 = 0.f, a2 = 0.f, a3 = 0.f;
            const float* wr = W_in + (size_t)k * H;
            for (int j = 0; j < H; j += 4) {
                float4 wi = __ldg((const float4*)(wr + j));
                float4 p0 = *(const float4*)(scr + 0 * H + j);
                float4 p1 = *(const float4*)(scr + 1 * H + j);
                float4 p2 = *(const float4*)(scr + 2 * H + j);
                float4 p3 = *(const float4*)(scr + 3 * H + j);
                a0 = fmaf(wi.x, p0.x, a0); a0 = fmaf(wi.y, p0.y, a0);
                a0 = fmaf(wi.z, p0.z, a0); a0 = fmaf(wi.w, p0.w, a0);
                a1 = fmaf(wi.x, p1.x, a1); a1 = fmaf(wi.y, p1.y, a1);
                a1 = fmaf(wi.z, p1.z, a1); a1 = fmaf(wi.w, p1.w, a1);
                a2 = fmaf(wi.x, p2.x, a2); a2 = fmaf(wi.y, p2.y, a2);
                a2 = fmaf(wi.z, p2.z, a2); a2 = fmaf(wi.w, p2.w, a2);
                a3 = fmaf(wi.x, p3.x, a3); a3 = fmaf(wi.y, p3.y, a3);
                a3 = fmaf(wi.z, p3.z, a3); a3 = fmaf(wi.w, p3.w, a3);
            }
            g_wfp[(size_t)(wfc0 + 0) * KIN + k] = a0;
            g_wfp[(size_t)(wfc0 + 1) * KIN + k] = a1;
            g_wfp[(size_t)(wfc0 + 2) * KIN + k] = a2;
            g_wfp[(size_t)(wfc0 + 3) * KIN + k] = a3;
        }
    }
    ALLBAR();   // all fused columns visible

    // load this CTA's 16 fused columns into SMEM
    for (int idx = tid; idx < KIN * COLS; idx += TPB) {
        int k = idx >> 4, cl = idx & 15;
        sWfp[cl * WS_IN + k] = g_wfp[(size_t)(colbase + cl) * KIN + k];
    }
    __syncthreads();

    // tile coordinates: 16 tiles (4x4) x 16-way split-K for both phases
    const int sC  = tid & 15;             // split id
    const int tlC = tid >> 4;             // tile id
    const int rC  = (tlC & 1) * 4;        // row base 0/4
    const int cC  = (tlC >> 1) * 4;       // col base 0..28 (32 logical cols)

    for (int st = 0; st < NSTEPS; ++st) {
        const bool enc = (st < SEQ);

        // ===== Phase 1: [h_pre | p] = concat(h0,x) @ [W_in | Wf]; h = mix =====
        {
            if (enc) {   // x_t prefetch BEFORE the flag wait
                int row = tid >> 5, iq = tid & 31;
                float4 v = __ldg((const float4*)(x + ((size_t)(b0 + row) * SEQ + st) * IDIM) + iq);
                *((float4*)(chs + row * KIN + H) + iq) = v;
            }
            WAIT_FLAGS(2 * st + 1);
            for (int i = tid; i < (BG * H) / 4; i += TPB) {
                int row = i >> 7, kq = i & 127;
                *((float4*)(chs + row * KIN) + kq) = __ldcg((const float4*)g_h0[g] + i);
            }
            __syncthreads();

            ull acc[4][4] = {};
            const int nj = enc ? 10 : 8;             // K=640 or 512
            for (int j = 0; j < nj; ++j) {
                const int k = sC * 4 + j * 64;
                double2 hd[4], wd[4];
#pragma unroll
                for (int r = 0; r < 4; ++r)
                    hd[r] = *(const double2*)(chs + (rC + r) * KIN + k);
#pragma unroll
                for (int c = 0; c < 4; ++c) {
                    const int lc = cC + c;           // 0..31, tile stays one side
                    const float* wb = (lc < 16) ? (sWin + lc * WS_IN)
                                                : (sWfp + (lc - 16) * WS_IN);
                    wd[c] = *(const double2*)(wb + k);
                }
                fma16x2(hd, wd, acc);
            }
#pragma unroll
            for (int r = 0; r < 4; ++r)
#pragma unroll
                for (int c = 0; c < 4; ++c)
                    scr[((rC + r) * 32 + cC + c) * 17 + sC] = pk_sum(acc[r][c]);
            __syncthreads();

            {   // reduce: 256 threads, one output each (row, lc)
                float v = 0.f;
#pragma unroll 8
                for (int s2 = 0; s2 < 16; ++s2) v += scr[tid * 17 + s2];
                tmp[tid] = v;
            }
            __syncthreads();

            if (tid < 128) {   // local mix -> h
                const int row = tid >> 4, cl = tid & 15;
                float hpre = tmp[row * 32 + cl]      + sbin[cl];
                float pv   = tmp[row * 32 + 16 + cl] + sbp[cl];
                float hv;
                if (enc) {
                    float m = (st < slen[row]) ? 1.f : 0.f;
                    hv = m * pv + (1.f - m) * hpre;
                } else {
                    hv = pv;
                }
                t_h[tid] = hv;
                g_hmix[g][row * H + colbase + cl] = hv;
            }
        }
        PUBLISH(2 * st + 2);

        if (!enc) {
            // decode output: out = h0 @ W_out + b_out  (h0 still staged in chs)
            __syncthreads();
            const int oo = tid >> 4, kp = tid & 15;
            const int row = oo >> 1, c = oo & 1;
            const float* hr = chs + row * KIN + kp * 32;
            const float* wr = sWout + c * WS_H + kp * 32;
            float a = 0.f;
#pragma unroll
            for (int k = 0; k < 32; k += 4) {
                float4 h4 = *(const float4*)(hr + k);
                float4 w4 = *(const float4*)(wr + k);
                a = fmaf(h4.x, w4.x, a); a = fmaf(h4.y, w4.y, a);
                a = fmaf(h4.z, w4.z, a); a = fmaf(h4.w, w4.w, a);
            }
            scr[tid] = a;
            __syncthreads();
            if (tid < 16) {
                float s = 0.f;
#pragma unroll
                for (int j = 0; j < 16; ++j) s += scr[tid * 16 + j];
                const int row2 = tid >> 1, c2 = tid & 1;
                const int td = st - SEQ;
                out[((size_t)(b0 + row2) * OUTLEN + td) * CDIM + oc0 + c2] = s + sbout[c2];
            }
        }

        // ===== Phase 2: tau/mem gates from h + ring update =====
        {
            WAIT_FLAGS(2 * st + 2);
            for (int i = tid; i < (BG * H) / 4; i += TPB) {
                int row = i >> 7, kq = i & 127;
                *((float4*)(chs + row * KIN) + kq) = __ldcg((const float4*)g_hmix[g] + i);
            }
            __syncthreads();

            ull acc[4][4] = {};
#pragma unroll
            for (int j = 0; j < 8; ++j) {
                const int k = sC * 4 + j * 64;
                double2 hd[4], wd[4];
#pragma unroll
                for (int r = 0; r < 4; ++r)
                    hd[r] = *(const double2*)(chs + (rC + r) * KIN + k);
#pragma unroll
                for (int c = 0; c < 4; ++c) {
                    const int lc = cC + c;
                    const float* wb = (lc < 16) ? (sWtau + lc * WS_H)
                                                : (sWmem + (lc - 16) * WS_H);
                    wd[c] = *(const double2*)(wb + k);
                }
                fma16x2(hd, wd, acc);
            }
#pragma unroll
            for (int r = 0; r < 4; ++r)
#pragma unroll
                for (int c = 0; c < 4; ++c)
                    scr[((rC + r) * 32 + cC + c) * 17 + sC] = pk_sum(acc[r][c]);
            __syncthreads();

            {   // reduce + gate nonlinearity
                const int row = tid >> 5, lc = tid & 31;
                float v = 0.f;
#pragma unroll 8
                for (int s2 = 0; s2 < 16; ++s2) v += scr[tid * 17 + s2];
                if (lc < 16) {
                    v += sbtau[lc];
                    g_t[row * 16 + lc] = fminf(fmaxf(16.f * sigf(v), 1.f), 16.f);
                } else {
                    v += sbmem[lc - 16];
                    g_m[row * 16 + (lc - 16)] = sigf(v);
                }
            }
            __syncthreads();

            if (tid < 128) {
                const float tau = g_t[tid];
                const float ml  = g_m[tid];
                const float hv  = t_h[tid];
                ring[(st & (RINGD - 1)) * 128 + tid] = 0.f;   // retire consumed slot
#pragma unroll
                for (int jp = 1; jp <= 16; ++jp) {
                    const int slot = (st + jp) & (RINGD - 1);
                    const float w = ml / (1.f + fabsf(tau - (float)jp));
                    ring[slot * 128 + tid] += w * hv;
                }
                const float h0n = ring[((st + 1) & (RINGD - 1)) * 128 + tid];
                const int row2 = tid >> 4, cl2 = tid & 15;
                g_h0[g][row2 * H + colbase + cl2] = h0n;
            }
        }
        PUBLISH(2 * st + 3);
    }

    // drain all CTAs, then reset flags for the next graph replay
    ALLBAR();
    if (tid == 0) g_flg[(g * PCOLS + p) * 32] = 0u;
}

extern "C" void kernel_launch(void* const* d_in, const int* in_sizes, int n_in,
                              void* d_out, int out_size)
{
    int wi = 2;
    if (n_in > 2 && in_sizes[2] == 1) wi = 3;   // skip scalar out_lengths if present

    const float* x       = (const float*)d_in[0];
    const int*   lengths = (const int*)  d_in[1];
    const float* W_in    = (const float*)d_in[wi + 0];
    const float* b_in    = (const float*)d_in[wi + 1];
    const float* W_pass  = (const float*)d_in[wi + 2];
    const float* b_pass  = (const float*)d_in[wi + 3];
    const float* W_tau   = (const float*)d_in[wi + 4];
    const float* b_tau   = (const float*)d_in[wi + 5];
    const float* W_mem   = (const float*)d_in[wi + 6];
    const float* b_mem   = (const float*)d_in[wi + 7];
    const float* W_out   = (const float*)d_in[wi + 8];
    const float* b_out   = (const float*)d_in[wi + 9];

    cudaFuncSetAttribute(delay_rnn_kernel,
                         cudaFuncAttributeMaxDynamicSharedMemorySize, SMEM_BYTES);

    delay_rnn_kernel<<<NCTAS, TPB, SMEM_BYTES>>>(
        x, lengths, W_in, b_in, W_pass, b_pass, W_tau, b_tau,
        W_mem, b_mem, W_out, b_out, (float*)d_out);
}